// round 17
// baseline (speedup 1.0000x reference)
#include <cuda_runtime.h>
#include <stdint.h>
#include <math.h>

#define NB   64
#define TT   2048
#define DH   256
#define MTOT (NB * TT)

// A-chain covers k = 0..KA-1, B-chain k = KA..255 (KA chosen to balance
// A's 4*KA cyc against B's 4*KB + P-read + tanh).
#define KA 136
#define KB (DH - KA)   // 120

// ---------------------------------------------------------------------------
// XLA EmitFastTanh, with_fma=true (VERIFIED bit-exact): fused Horner,
// clamp +-7.99881172180175781, |x| < 0.0004 -> x, IEEE RN divide.
// ---------------------------------------------------------------------------
__device__ __forceinline__ float tanh_xla(float x) {
    float a  = fabsf(x);
    float xc = fminf(fmaxf(x, -7.99881172180175781f), 7.99881172180175781f);
    float x2 = xc * xc;
    float p = __fmaf_rn(x2, -2.76076847742355e-16f, 2.00018790482477e-13f);
    p = __fmaf_rn(x2, p, -8.60467152213735e-11f);
    p = __fmaf_rn(x2, p,  5.12229709037114e-08f);
    p = __fmaf_rn(x2, p,  1.48572235717979e-05f);
    p = __fmaf_rn(x2, p,  6.37261928875436e-04f);
    p = __fmaf_rn(x2, p,  4.89352455891786e-03f);
    p = xc * p;
    float q = __fmaf_rn(x2, 1.19825839466702e-06f, 1.18534705686654e-04f);
    q = __fmaf_rn(x2, q, 2.26843463243900e-03f);
    q = __fmaf_rn(x2, q, 4.89352518554385e-03f);
    float r = __fdiv_rn(p, q);
    return (a < 0.0004f) ? x : r;
}

// ===========================================================================
// Kernel A: out = X @ Wx + bx  (131072 x 256 x 256), bit-exact FFMA chain.
// Double-buffered smem (proven, unchanged).
// ===========================================================================
__global__ void __launch_bounds__(256)
xproj_kernel(const float* __restrict__ X, const float* __restrict__ W,
             const float* __restrict__ bx, float* __restrict__ out)
{
    __shared__ float As[2][8][128];
    __shared__ float Bs[2][8][128];

    const int tid = threadIdx.x;
    const int bm = blockIdx.x * 128;
    const int bn = blockIdx.y * 128;
    const int tx = tid & 15, ty = tid >> 4;
    const int m0 = ty * 8, n0 = tx * 8;
    const int arow = tid >> 1, acol4 = (tid & 1) * 4;
    const int brow = tid >> 5, bcol4 = (tid & 31) * 4;

    float acc[8][8];
    #pragma unroll
    for (int i = 0; i < 8; i++)
        #pragma unroll
        for (int j = 0; j < 8; j++) acc[i][j] = 0.f;

    float4 av = *(const float4*)&X[(size_t)(bm + arow) * DH + acol4];
    float4 bv = *(const float4*)&W[(size_t)brow * DH + bn + bcol4];
    As[0][acol4 + 0][arow] = av.x; As[0][acol4 + 1][arow] = av.y;
    As[0][acol4 + 2][arow] = av.z; As[0][acol4 + 3][arow] = av.w;
    *(float4*)&Bs[0][brow][bcol4] = bv;
    __syncthreads();

    #pragma unroll 4
    for (int it = 0; it < 32; it++) {
        const int cur = it & 1;
        if (it < 31) {
            const int k0 = (it + 1) * 8;
            av = *(const float4*)&X[(size_t)(bm + arow) * DH + k0 + acol4];
            bv = *(const float4*)&W[(size_t)(k0 + brow) * DH + bn + bcol4];
        }
        #pragma unroll
        for (int k = 0; k < 8; k++) {
            float a[8], b[8];
            *(float4*)(a)     = *(const float4*)&As[cur][k][m0];
            *(float4*)(a + 4) = *(const float4*)&As[cur][k][m0 + 4];
            *(float4*)(b)     = *(const float4*)&Bs[cur][k][n0];
            *(float4*)(b + 4) = *(const float4*)&Bs[cur][k][n0 + 4];
            #pragma unroll
            for (int i = 0; i < 8; i++)
                #pragma unroll
                for (int j = 0; j < 8; j++)
                    acc[i][j] = __fmaf_rn(a[i], b[j], acc[i][j]);
        }
        if (it < 31) {
            const int nxt = cur ^ 1;
            As[nxt][acol4 + 0][arow] = av.x; As[nxt][acol4 + 1][arow] = av.y;
            As[nxt][acol4 + 2][arow] = av.z; As[nxt][acol4 + 3][arow] = av.w;
            *(float4*)&Bs[nxt][brow][bcol4] = bv;
            __syncthreads();
        }
    }

    float bxr[8];
    #pragma unroll
    for (int j = 0; j < 8; j++) bxr[j] = bx[bn + n0 + j];
    #pragma unroll
    for (int i = 0; i < 8; i++) {
        const size_t row = (size_t)(bm + m0 + i);
        #pragma unroll
        for (int j = 0; j < 8; j += 4) {
            float4 v;
            v.x = __fadd_rn(acc[i][j+0], bxr[j+0]);
            v.y = __fadd_rn(acc[i][j+1], bxr[j+1]);
            v.z = __fadd_rn(acc[i][j+2], bxr[j+2]);
            v.w = __fadd_rn(acc[i][j+3], bxr[j+3]);
            *(float4*)&out[row * DH + bn + n0 + j] = v;
        }
    }
}

// ===========================================================================
// Kernel B: recurrence with SPLIT CHAIN (bit-exact: same fp32 op sequence).
// 512 threads/CTA, one CTA per batch. Threads 0..255 = role A (column c),
// threads 256..511 = role B (column c). Per step:
//   A: acc = FFMA chain k=0..KA-1 (w in 136 regs, h via pipelined LDS.128)
//      -> P[c] (exact partial)
//   barrier
//   B: acc = P[c]; continue chain k=KA..255 (w in 120 regs);
//      pre=(xp+acc)+bh; h=tanh_xla(pre); hnxt[c]=h; out=h
//   barrier
// Wh entirely in registers -> zero smem weight traffic. B prefetches xp and
// its first h operands during A's phase.
// ===========================================================================
__global__ void __launch_bounds__(512, 1)
rnn_rec_kernel(const float* __restrict__ Wh, const float* __restrict__ bh,
               const float* __restrict__ h_init, float* __restrict__ out)
{
    __shared__ float hA[DH];
    __shared__ float hB[DH];
    __shared__ float P[DH];

    const int b   = blockIdx.x;
    const int tid = threadIdx.x;
    const bool roleA = (tid < 256);
    const int c   = tid & 255;

    // per-role weight registers
    float wreg[KA];                      // A uses all 136; B uses first 120
    if (roleA) {
        #pragma unroll
        for (int k = 0; k < KA; k++)
            wreg[k] = Wh[(size_t)k * DH + c];
    } else {
        #pragma unroll
        for (int k = 0; k < KB; k++)
            wreg[k] = Wh[(size_t)(KA + k) * DH + c];
    }

    if (roleA) hA[c] = h_init[(size_t)b * DH + c];
    const float bias = bh[c];            // only B consumes
    __syncthreads();

    float* hcur = hA;
    float* hnxt = hB;
    float* obase = out + (size_t)b * TT * DH + c;

    for (int t = 0; t < TT; t++) {
        float xp;
        float4 f0, f1;

        if (roleA) {
            // ---- A phase: chain k = 0..135 (34 float4 chunks) ----
            const float4* h4 = (const float4*)hcur;
            float acc = 0.f;
            float4 a0 = h4[0], a1 = h4[1];
            #pragma unroll
            for (int ch = 0; ch < 34; ch++) {
                float4 an;
                if (ch < 32) an = h4[ch + 2];
                acc = __fmaf_rn(a0.x, wreg[ch * 4 + 0], acc);
                acc = __fmaf_rn(a0.y, wreg[ch * 4 + 1], acc);
                acc = __fmaf_rn(a0.z, wreg[ch * 4 + 2], acc);
                acc = __fmaf_rn(a0.w, wreg[ch * 4 + 3], acc);
                a0 = a1; a1 = an;
            }
            P[c] = acc;
        } else {
            // B prefetches during A's phase (values stable: h(t-1) complete)
            xp = obase[(size_t)t * DH];
            const float4* h4b = (const float4*)(hcur + KA);
            f0 = h4b[0];
            f1 = h4b[1];
        }

        __syncthreads();   // P complete; A's hcur reads done

        if (!roleA) {
            // ---- B phase: continue chain k = 136..255 (30 float4 chunks) ----
            const float4* h4b = (const float4*)(hcur + KA);
            float acc = P[c];
            #pragma unroll
            for (int ch = 0; ch < 30; ch++) {
                float4 fn;
                if (ch < 28) fn = h4b[ch + 2];
                acc = __fmaf_rn(f0.x, wreg[ch * 4 + 0], acc);
                acc = __fmaf_rn(f0.y, wreg[ch * 4 + 1], acc);
                acc = __fmaf_rn(f0.z, wreg[ch * 4 + 2], acc);
                acc = __fmaf_rn(f0.w, wreg[ch * 4 + 3], acc);
                f0 = f1; f1 = fn;
            }
            float pre = __fadd_rn(__fadd_rn(xp, acc), bias);
            float h = tanh_xla(pre);
            hnxt[c] = h;
            obase[(size_t)t * DH] = h;
        }

        __syncthreads();   // hnxt complete

        float* tmp = hcur; hcur = hnxt; hnxt = tmp;
    }
}

// ===========================================================================
extern "C" void kernel_launch(void* const* d_in, const int* in_sizes, int n_in,
                              void* d_out, int out_size)
{
    const float* seq_x  = (const float*)d_in[0];
    const float* Wx     = (const float*)d_in[1];
    const float* bx     = (const float*)d_in[2];
    const float* Wh     = (const float*)d_in[3];
    const float* bh     = (const float*)d_in[4];
    const float* h_init = (const float*)d_in[5];
    float* out = (float*)d_out;

    xproj_kernel<<<dim3(MTOT / 128, DH / 128), 256>>>(seq_x, Wx, bx, out);

    rnn_rec_kernel<<<NB, 512>>>(Wh, bh, h_init, out);
}